// round 1
// baseline (speedup 1.0000x reference)
#include <cuda_runtime.h>
#include <math.h>

#define NN    100000
#define EE    1600000
#define CC    128
#define FIN   64
#define NSTEP 4
#define NEG_SLOPE 0.01f

// ---------------- scratch (static device globals; no runtime allocation) ----------------
__device__ __align__(256) float g_h  [(size_t)NN * CC];
__device__ __align__(256) float g_m  [(size_t)NN * CC];
__device__ __align__(256) float g_agg[(size_t)NN * CC];
__device__ __align__(256) float g_G  [(size_t)NN * 3 * CC];
__device__ __align__(256) float g_Hn [(size_t)NN * CC];
__device__ __align__(256) float g_Wt [CC * CC];
__device__ int   g_deg[NN];
__device__ int   g_rowstart[NN + 1];
__device__ int   g_cursor[NN];
__device__ int   g_csrsrc[EE];
__device__ int   g_blocksum[128];
__device__ int   g_blockoff[128];
__device__ int   g_is64;
__device__ float g_colsum[CC];

// ---------------- edge dtype detection ----------------
// If the harness delivered int32 indices, reading them as int64 pairs lo+hi*2^32
// gives huge values with overwhelming probability (hi is a node index, ==0 w.p. ~1e-5).
__global__ void detect_k(const void* __restrict__ edges) {
    if (threadIdx.x == 0 && blockIdx.x == 0) {
        const long long* p = (const long long*)edges;
        int is64 = 1;
        for (int i = 0; i < 256; i++) {
            long long v = p[i];
            if (v < 0 || v >= (long long)NN) { is64 = 0; break; }
        }
        g_is64 = is64;
    }
}

__device__ __forceinline__ int edge_at(const void* edges, int which, int e, bool is64) {
    if (is64) return (int)((const long long*)edges)[(size_t)which * EE + e];
    return ((const int*)edges)[(size_t)which * EE + e];
}

// ---------------- CSR build ----------------
__global__ void zero_deg_k() {
    for (int i = blockIdx.x * blockDim.x + threadIdx.x; i < NN; i += gridDim.x * blockDim.x)
        g_deg[i] = 0;
}

__global__ void hist_k(const void* __restrict__ edges) {
    bool is64 = g_is64;
    for (int e = blockIdx.x * blockDim.x + threadIdx.x; e < EE; e += gridDim.x * blockDim.x) {
        int dst = edge_at(edges, 1, e, is64);
        atomicAdd(&g_deg[dst], 1);
    }
}

__global__ void scan1_k() {
    __shared__ int s[1024];
    int tid = threadIdx.x;
    int i = blockIdx.x * 1024 + tid;
    int v = (i < NN) ? g_deg[i] : 0;
    s[tid] = v;
    __syncthreads();
    for (int off = 1; off < 1024; off <<= 1) {
        int t = (tid >= off) ? s[tid - off] : 0;
        __syncthreads();
        s[tid] += t;
        __syncthreads();
    }
    if (i < NN) g_rowstart[i] = s[tid] - v;   // exclusive within block
    if (tid == 1023) g_blocksum[blockIdx.x] = s[1023];
}

__global__ void scan2_k(int nb) {
    if (threadIdx.x == 0 && blockIdx.x == 0) {
        int acc = 0;
        for (int b = 0; b < nb; b++) { int t = g_blocksum[b]; g_blockoff[b] = acc; acc += t; }
        g_rowstart[NN] = acc;
    }
}

__global__ void scan3_k() {
    int i = blockIdx.x * 1024 + threadIdx.x;
    if (i < NN) {
        int v = g_rowstart[i] + g_blockoff[blockIdx.x];
        g_rowstart[i] = v;
        g_cursor[i] = v;
    }
}

__global__ void scatter_k(const void* __restrict__ edges) {
    bool is64 = g_is64;
    for (int e = blockIdx.x * blockDim.x + threadIdx.x; e < EE; e += gridDim.x * blockDim.x) {
        int src = edge_at(edges, 0, e, is64);
        int dst = edge_at(edges, 1, e, is64);
        int pos = atomicAdd(&g_cursor[dst], 1);
        g_csrsrc[pos] = src;
    }
}

// ---------------- generic NT SGEMM:  C[M,Ntile] = A[M,K] * B[N,K]^T ----------------
// A and B each may be split along K at KA0/KB0 into two row-major sources
// (used to form [agg|h] @ [W_ih|W_hh]^T without materializing the concat).
__global__ void __launch_bounds__(256, 2) sgemm_nt(
    const float* __restrict__ A0, int lda0,
    const float* __restrict__ A1, int lda1, int KA0,
    const float* __restrict__ B0, int ldb0,
    const float* __restrict__ B1, int ldb1, int KB0,
    float* __restrict__ Cm, int ldc, int M, int Ktot)
{
    constexpr int BM = 128, BN = 128, BK = 16;
    __shared__ float As[BK][BM];
    __shared__ float Bs[BK][BN];
    const int tid = threadIdx.x;
    const int row0 = blockIdx.x * BM;
    const int col0 = blockIdx.y * BN;
    const int tx = tid & 15;
    const int ty = tid >> 4;

    float acc[8][8];
#pragma unroll
    for (int i = 0; i < 8; i++)
#pragma unroll
        for (int j = 0; j < 8; j++) acc[i][j] = 0.f;

    for (int kt = 0; kt < Ktot; kt += BK) {
#pragma unroll
        for (int it = 0; it < 2; ++it) {
            int idx = tid + it * 256;
            int r   = idx >> 2;
            int k4  = (idx & 3) << 2;
            int gk  = kt + k4;

            // A tile (M-guarded, zero-fill)
            float4 va = make_float4(0.f, 0.f, 0.f, 0.f);
            int grow = row0 + r;
            if (grow < M) {
                const float* Ap; int kk;
                if (gk < KA0) { Ap = A0 + (size_t)grow * lda0; kk = gk; }
                else          { Ap = A1 + (size_t)grow * lda1; kk = gk - KA0; }
                va = *reinterpret_cast<const float4*>(Ap + kk);
            }
            As[k4 + 0][r] = va.x; As[k4 + 1][r] = va.y;
            As[k4 + 2][r] = va.z; As[k4 + 3][r] = va.w;

            // B tile (N dims are exact multiples of 128 here; no guard)
            const float* Bp; int kkb;
            int gcol = col0 + r;
            if (gk < KB0) { Bp = B0 + (size_t)gcol * ldb0; kkb = gk; }
            else          { Bp = B1 + (size_t)gcol * ldb1; kkb = gk - KB0; }
            float4 vb = *reinterpret_cast<const float4*>(Bp + kkb);
            Bs[k4 + 0][r] = vb.x; Bs[k4 + 1][r] = vb.y;
            Bs[k4 + 2][r] = vb.z; Bs[k4 + 3][r] = vb.w;
        }
        __syncthreads();

#pragma unroll
        for (int k = 0; k < BK; k++) {
            float af[8], bf[8];
            *reinterpret_cast<float4*>(af)     = *reinterpret_cast<const float4*>(&As[k][ty * 8]);
            *reinterpret_cast<float4*>(af + 4) = *reinterpret_cast<const float4*>(&As[k][ty * 8 + 4]);
            *reinterpret_cast<float4*>(bf)     = *reinterpret_cast<const float4*>(&Bs[k][tx * 8]);
            *reinterpret_cast<float4*>(bf + 4) = *reinterpret_cast<const float4*>(&Bs[k][tx * 8 + 4]);
#pragma unroll
            for (int i = 0; i < 8; i++)
#pragma unroll
                for (int j = 0; j < 8; j++)
                    acc[i][j] = fmaf(af[i], bf[j], acc[i][j]);
        }
        __syncthreads();
    }

#pragma unroll
    for (int i = 0; i < 8; i++) {
        int grow = row0 + ty * 8 + i;
        if (grow < M) {
            float* Cp = Cm + (size_t)grow * ldc + col0 + tx * 8;
            *reinterpret_cast<float4*>(Cp)     = make_float4(acc[i][0], acc[i][1], acc[i][2], acc[i][3]);
            *reinterpret_cast<float4*>(Cp + 4) = make_float4(acc[i][4], acc[i][5], acc[i][6], acc[i][7]);
        }
    }
}

// ---------------- per-step helpers ----------------
__global__ void transpose_k(const float* __restrict__ W) {
    int idx = blockIdx.x * blockDim.x + threadIdx.x;   // 16384 = 128*128
    int k = idx & 127;
    g_Wt[idx] = W[(size_t)k * CC + (idx >> 7)];        // Wt[c][k] = W[k][c]
}

// one warp per node: agg[v] = sum over in-edges of m[src]
__global__ void aggregate_k() {
    int warp = (blockIdx.x * blockDim.x + threadIdx.x) >> 5;
    int lane = threadIdx.x & 31;
    if (warp >= NN) return;
    const float4* m4 = reinterpret_cast<const float4*>(g_m);
    int s = g_rowstart[warp], e = g_rowstart[warp + 1];
    float4 acc = make_float4(0.f, 0.f, 0.f, 0.f);
    int i = s;
    for (; i + 4 <= e; i += 4) {
        int s0 = g_csrsrc[i], s1 = g_csrsrc[i + 1], s2 = g_csrsrc[i + 2], s3 = g_csrsrc[i + 3];
        float4 v0 = m4[(size_t)s0 * 32 + lane];
        float4 v1 = m4[(size_t)s1 * 32 + lane];
        float4 v2 = m4[(size_t)s2 * 32 + lane];
        float4 v3 = m4[(size_t)s3 * 32 + lane];
        acc.x += (v0.x + v1.x) + (v2.x + v3.x);
        acc.y += (v0.y + v1.y) + (v2.y + v3.y);
        acc.z += (v0.z + v1.z) + (v2.z + v3.z);
        acc.w += (v0.w + v1.w) + (v2.w + v3.w);
    }
    for (; i < e; ++i) {
        float4 v = m4[(size_t)g_csrsrc[i] * 32 + lane];
        acc.x += v.x; acc.y += v.y; acc.z += v.z; acc.w += v.w;
    }
    reinterpret_cast<float4*>(g_agg)[(size_t)warp * 32 + lane] = acc;
}

// GRU gates from G = gi+gh (raw, no bias) and Hn = gh_n (raw):
//   r = sig(G_r + bih_r + bhh_r); z = sig(G_z + bih_z + bhh_z)
//   n = tanh( (G_n - Hn) + bih_n + r * (Hn + bhh_n) )
//   h = (1-z)*n + z*h
__global__ void gate_k(const float* __restrict__ bih, const float* __restrict__ bhh) {
    int idx = blockIdx.x * blockDim.x + threadIdx.x;   // NN*CC threads
    if (idx >= NN * CC) return;
    int c = idx & (CC - 1);
    size_t n = (size_t)(idx >> 7);
    const float* Gp = g_G + n * (3 * CC);
    float Gr = Gp[c], Gz = Gp[CC + c], Gn = Gp[2 * CC + c];
    float Hnv = g_Hn[n * CC + c];
    float r = 1.f / (1.f + expf(-(Gr + bih[c] + bhh[c])));
    float z = 1.f / (1.f + expf(-(Gz + bih[CC + c] + bhh[CC + c])));
    float nn = tanhf((Gn - Hnv) + bih[2 * CC + c] + r * (Hnv + bhh[2 * CC + c]));
    float h = g_h[n * CC + c];
    g_h[n * CC + c] = (1.f - z) * nn + z * h;
}

// ---------------- readout ----------------
__global__ void zero_colsum_k() { if (threadIdx.x < CC) g_colsum[threadIdx.x] = 0.f; }

__global__ void reduce_cols_k() {
    int c = threadIdx.x;   // blockDim = 128
    float acc = 0.f;
    for (int n = blockIdx.x; n < NN; n += gridDim.x) {
        float v = g_h[(size_t)n * CC + c];
        acc += (v >= 0.f) ? v : NEG_SLOPE * v;
    }
    atomicAdd(&g_colsum[c], acc);
}

__global__ void finalize_k(const float* __restrict__ wpred, const float* __restrict__ bpred,
                           float* __restrict__ out) {
    int lane = threadIdx.x;   // 32 threads
    float s = 0.f;
    for (int c = lane; c < CC; c += 32) s += g_colsum[c] * wpred[c];
    for (int o = 16; o; o >>= 1) s += __shfl_xor_sync(0xFFFFFFFFu, s, o);
    if (lane == 0) out[0] = s * (1.0f / (float)NN) + bpred[0];
}

// ---------------- launch ----------------
extern "C" void kernel_launch(void* const* d_in, const int* in_sizes, int n_in,
                              void* d_out, int out_size) {
    const float* x      = (const float*)d_in[0];
    const void*  edges  = d_in[1];
    const float* W_in   = (const float*)d_in[2];
    const float* W_mpnn = (const float*)d_in[3];
    const float* W_ih   = (const float*)d_in[4];
    const float* W_hh   = (const float*)d_in[5];
    const float* b_ih   = (const float*)d_in[6];
    const float* b_hh   = (const float*)d_in[7];
    const float* W_pred = (const float*)d_in[8];
    const float* b_pred = (const float*)d_in[9];
    float* out = (float*)d_out;

    // device-global addresses for the generic gemm
    void *p_h, *p_m, *p_agg, *p_G, *p_Hn, *p_Wt;
    cudaGetSymbolAddress(&p_h,   g_h);
    cudaGetSymbolAddress(&p_m,   g_m);
    cudaGetSymbolAddress(&p_agg, g_agg);
    cudaGetSymbolAddress(&p_G,   g_G);
    cudaGetSymbolAddress(&p_Hn,  g_Hn);
    cudaGetSymbolAddress(&p_Wt,  g_Wt);
    float* h_  = (float*)p_h;
    float* m_  = (float*)p_m;
    float* ag_ = (float*)p_agg;
    float* G_  = (float*)p_G;
    float* Hn_ = (float*)p_Hn;
    float* Wt_ = (float*)p_Wt;

    const int NB = (NN + 1023) / 1024;   // 98

    // CSR build (runs every replay; same graph every call -> deterministic work)
    detect_k<<<1, 32>>>(edges);
    zero_deg_k<<<128, 256>>>();
    hist_k<<<512, 256>>>(edges);
    scan1_k<<<NB, 1024>>>();
    scan2_k<<<1, 32>>>(NB);
    scan3_k<<<NB, 1024>>>();
    scatter_k<<<512, 256>>>(edges);

    dim3 grid1((NN + 127) / 128, 1);
    dim3 grid3((NN + 127) / 128, 3);

    // h = x @ W_in^T   (M=NN, N=128, K=64)
    sgemm_nt<<<grid1, 256>>>(x, FIN, x, FIN, FIN,
                             W_in, FIN, W_in, FIN, FIN,
                             h_, CC, NN, FIN);

    for (int step = 0; step < NSTEP; ++step) {
        // Wt = W_mpnn[step]^T, then m = h @ W_mpnn[step] = h @ Wt^T
        transpose_k<<<64, 256>>>(W_mpnn + (size_t)step * CC * CC);
        sgemm_nt<<<grid1, 256>>>(h_, CC, h_, CC, CC,
                                 Wt_, CC, Wt_, CC, CC,
                                 m_, CC, NN, CC);

        // agg = scatter_add(m[src] -> dst) via CSR gather
        aggregate_k<<<NN / 8, 256>>>();

        // G = [agg | h] @ [W_ih | W_hh]^T   (M=NN, N=384, K=256)
        sgemm_nt<<<grid3, 256>>>(ag_, CC, h_, CC, CC,
                                 W_ih, CC, W_hh, CC, CC,
                                 G_, 3 * CC, NN, 2 * CC);

        // Hn = h @ W_hh[2C:,:]^T   (M=NN, N=128, K=128)
        sgemm_nt<<<grid1, 256>>>(h_, CC, h_, CC, CC,
                                 W_hh + 2 * CC * CC, CC, W_hh + 2 * CC * CC, CC, CC,
                                 Hn_, CC, NN, CC);

        gate_k<<<(NN * CC) / 256, 256>>>(b_ih, b_hh);
    }

    // leaky-relu -> column sums -> dot with W_pred, divide by N
    zero_colsum_k<<<1, 128>>>();
    reduce_cols_k<<<2048, 128>>>();
    finalize_k<<<1, 32>>>(W_pred, b_pred, out);
}

// round 2
// speedup vs baseline: 1.9278x; 1.9278x over previous
#include <cuda_runtime.h>
#include <math.h>
#include <stdint.h>

#define NN    100000
#define EE    1600000
#define CC    128
#define FIN   64
#define NSTEP 4
#define NEG_SLOPE 0.01f

// ---------------- scratch (static device globals; no runtime allocation) ----------------
__device__ __align__(256) float g_h  [(size_t)NN * CC];
__device__ __align__(256) float g_m  [(size_t)NN * CC];
__device__ __align__(256) float g_agg[(size_t)NN * CC];
__device__ __align__(256) float g_G  [(size_t)NN * 3 * CC];
__device__ __align__(256) float g_Hn [(size_t)NN * CC];
__device__ __align__(256) float g_Wt [CC * CC];
__device__ int   g_deg[NN];
__device__ int   g_rowstart[NN + 1];
__device__ int   g_cursor[NN];
__device__ int   g_csrsrc[EE];
__device__ int   g_blocksum[128];
__device__ int   g_blockoff[128];
__device__ int   g_is64;
__device__ float g_colsum[CC];

// ---------------- edge dtype detection ----------------
__global__ void detect_k(const void* __restrict__ edges) {
    if (threadIdx.x == 0 && blockIdx.x == 0) {
        const long long* p = (const long long*)edges;
        int is64 = 1;
        for (int i = 0; i < 256; i++) {
            long long v = p[i];
            if (v < 0 || v >= (long long)NN) { is64 = 0; break; }
        }
        g_is64 = is64;
    }
}

__device__ __forceinline__ int edge_at(const void* edges, int which, int e, bool is64) {
    if (is64) return (int)((const long long*)edges)[(size_t)which * EE + e];
    return ((const int*)edges)[(size_t)which * EE + e];
}

// ---------------- CSR build ----------------
__global__ void zero_deg_k() {
    for (int i = blockIdx.x * blockDim.x + threadIdx.x; i < NN; i += gridDim.x * blockDim.x)
        g_deg[i] = 0;
}

__global__ void hist_k(const void* __restrict__ edges) {
    bool is64 = g_is64;
    for (int e = blockIdx.x * blockDim.x + threadIdx.x; e < EE; e += gridDim.x * blockDim.x) {
        int dst = edge_at(edges, 1, e, is64);
        atomicAdd(&g_deg[dst], 1);
    }
}

__global__ void scan1_k() {
    __shared__ int s[1024];
    int tid = threadIdx.x;
    int i = blockIdx.x * 1024 + tid;
    int v = (i < NN) ? g_deg[i] : 0;
    s[tid] = v;
    __syncthreads();
    for (int off = 1; off < 1024; off <<= 1) {
        int t = (tid >= off) ? s[tid - off] : 0;
        __syncthreads();
        s[tid] += t;
        __syncthreads();
    }
    if (i < NN) g_rowstart[i] = s[tid] - v;
    if (tid == 1023) g_blocksum[blockIdx.x] = s[1023];
}

__global__ void scan2_k(int nb) {
    if (threadIdx.x == 0 && blockIdx.x == 0) {
        int acc = 0;
        for (int b = 0; b < nb; b++) { int t = g_blocksum[b]; g_blockoff[b] = acc; acc += t; }
        g_rowstart[NN] = acc;
    }
}

__global__ void scan3_k() {
    int i = blockIdx.x * 1024 + threadIdx.x;
    if (i < NN) {
        int v = g_rowstart[i] + g_blockoff[blockIdx.x];
        g_rowstart[i] = v;
        g_cursor[i] = v;
    }
}

__global__ void scatter_k(const void* __restrict__ edges) {
    bool is64 = g_is64;
    for (int e = blockIdx.x * blockDim.x + threadIdx.x; e < EE; e += gridDim.x * blockDim.x) {
        int src = edge_at(edges, 0, e, is64);
        int dst = edge_at(edges, 1, e, is64);
        int pos = atomicAdd(&g_cursor[dst], 1);
        g_csrsrc[pos] = src;
    }
}

// ---------------- tf32 tensor-core NT GEMM:  C[M,N] = A[M,K] * B[N,K]^T ----------------
// A and B may each be split along K at KA0/KB0 into two row-major fp32 sources.
// BM=128, BN=128, BK=16. 256 threads = 8 warps in a 2x4 grid; warp tile 64x32.
// Smem layout stride 20 words -> conflict-free m16n8k8 fragment loads
// (banks (g*20+t)%32 = {0,20,8,28,16,4,24,12}+t, all distinct).

__device__ __forceinline__ uint32_t f2tf32(float f) {
    uint32_t u;
    asm volatile("cvt.rna.tf32.f32 %0, %1;" : "=r"(u) : "f"(f));
    return u;
}

__device__ __forceinline__ void mma_tf32(float* d, const uint32_t* a, const uint32_t* b) {
    asm volatile(
        "mma.sync.aligned.m16n8k8.row.col.f32.tf32.tf32.f32 "
        "{%0,%1,%2,%3}, {%4,%5,%6,%7}, {%8,%9}, {%0,%1,%2,%3};"
        : "+f"(d[0]), "+f"(d[1]), "+f"(d[2]), "+f"(d[3])
        : "r"(a[0]), "r"(a[1]), "r"(a[2]), "r"(a[3]), "r"(b[0]), "r"(b[1]));
}

#define SM_STRIDE 20

__global__ void __launch_bounds__(256, 2) mma_gemm_nt(
    const float* __restrict__ A0, int lda0,
    const float* __restrict__ A1, int lda1, int KA0,
    const float* __restrict__ B0, int ldb0,
    const float* __restrict__ B1, int ldb1, int KB0,
    float* __restrict__ Cm, int ldc, int M, int Ktot)
{
    __shared__ uint32_t As[128 * SM_STRIDE];
    __shared__ uint32_t Bs[128 * SM_STRIDE];

    const int tid  = threadIdx.x;
    const int lane = tid & 31;
    const int warp = tid >> 5;
    const int wr   = warp & 1;        // 0..1 -> 64-row strip
    const int wc   = warp >> 1;       // 0..3 -> 32-col strip
    const int g    = lane >> 2;       // groupID
    const int t    = lane & 3;        // thread-in-group

    const int row0 = blockIdx.x * 128;
    const int col0 = blockIdx.y * 128;

    float acc[4][4][4];
#pragma unroll
    for (int i = 0; i < 4; i++)
#pragma unroll
        for (int j = 0; j < 4; j++)
#pragma unroll
            for (int k = 0; k < 4; k++) acc[i][j][k] = 0.f;

    for (int kt = 0; kt < Ktot; kt += 16) {
        // ---- load A tile (128x16), M-guarded zero-fill ----
#pragma unroll
        for (int it = 0; it < 2; ++it) {
            int idx = tid + it * 256;
            int r   = idx >> 2;
            int k4  = (idx & 3) << 2;
            int gk  = kt + k4;
            float4 va = make_float4(0.f, 0.f, 0.f, 0.f);
            int grow = row0 + r;
            if (grow < M) {
                const float* Ap; int kk;
                if (gk < KA0) { Ap = A0 + (size_t)grow * lda0; kk = gk; }
                else          { Ap = A1 + (size_t)grow * lda1; kk = gk - KA0; }
                va = *reinterpret_cast<const float4*>(Ap + kk);
            }
            *reinterpret_cast<uint4*>(&As[r * SM_STRIDE + k4]) =
                make_uint4(f2tf32(va.x), f2tf32(va.y), f2tf32(va.z), f2tf32(va.w));

            // ---- B tile (128x16), N multiples of 128 -> no guard ----
            const float* Bp; int kkb;
            int gcol = col0 + r;
            if (gk < KB0) { Bp = B0 + (size_t)gcol * ldb0; kkb = gk; }
            else          { Bp = B1 + (size_t)gcol * ldb1; kkb = gk - KB0; }
            float4 vb = *reinterpret_cast<const float4*>(Bp + kkb);
            *reinterpret_cast<uint4*>(&Bs[r * SM_STRIDE + k4]) =
                make_uint4(f2tf32(vb.x), f2tf32(vb.y), f2tf32(vb.z), f2tf32(vb.w));
        }
        __syncthreads();

        // ---- compute: 2 k8 chunks ----
#pragma unroll
        for (int kk = 0; kk < 16; kk += 8) {
            uint32_t a[4][4], b[4][2];
#pragma unroll
            for (int mt = 0; mt < 4; mt++) {
                int base = (wr * 64 + mt * 16 + g) * SM_STRIDE + kk + t;
                a[mt][0] = As[base];
                a[mt][1] = As[base + 8 * SM_STRIDE];
                a[mt][2] = As[base + 4];
                a[mt][3] = As[base + 8 * SM_STRIDE + 4];
            }
#pragma unroll
            for (int nt = 0; nt < 4; nt++) {
                int base = (wc * 32 + nt * 8 + g) * SM_STRIDE + kk + t;
                b[nt][0] = Bs[base];
                b[nt][1] = Bs[base + 4];
            }
#pragma unroll
            for (int mt = 0; mt < 4; mt++)
#pragma unroll
                for (int nt = 0; nt < 4; nt++)
                    mma_tf32(acc[mt][nt], a[mt], b[nt]);
        }
        __syncthreads();
    }

    // ---- epilogue: c0,c1 at (row g, col 2t,2t+1); c2,c3 at row g+8 ----
#pragma unroll
    for (int mt = 0; mt < 4; mt++) {
        int rbase = row0 + wr * 64 + mt * 16 + g;
#pragma unroll
        for (int nt = 0; nt < 4; nt++) {
            int col = col0 + wc * 32 + nt * 8 + 2 * t;
            if (rbase < M) {
                float2 v0 = make_float2(acc[mt][nt][0], acc[mt][nt][1]);
                *reinterpret_cast<float2*>(Cm + (size_t)rbase * ldc + col) = v0;
            }
            if (rbase + 8 < M) {
                float2 v1 = make_float2(acc[mt][nt][2], acc[mt][nt][3]);
                *reinterpret_cast<float2*>(Cm + (size_t)(rbase + 8) * ldc + col) = v1;
            }
        }
    }
}

// ---------------- per-step helpers ----------------
__global__ void transpose_k(const float* __restrict__ W) {
    int idx = blockIdx.x * blockDim.x + threadIdx.x;   // 16384 = 128*128
    int k = idx & 127;
    g_Wt[idx] = W[(size_t)k * CC + (idx >> 7)];        // Wt[c][k] = W[k][c]
}

// one warp per node: agg[v] = sum over in-edges of m[src]
__global__ void aggregate_k() {
    int warp = (blockIdx.x * blockDim.x + threadIdx.x) >> 5;
    int lane = threadIdx.x & 31;
    if (warp >= NN) return;
    const float4* m4 = reinterpret_cast<const float4*>(g_m);
    int s = g_rowstart[warp], e = g_rowstart[warp + 1];
    float4 acc = make_float4(0.f, 0.f, 0.f, 0.f);
    int i = s;
    for (; i + 4 <= e; i += 4) {
        int s0 = g_csrsrc[i], s1 = g_csrsrc[i + 1], s2 = g_csrsrc[i + 2], s3 = g_csrsrc[i + 3];
        float4 v0 = m4[(size_t)s0 * 32 + lane];
        float4 v1 = m4[(size_t)s1 * 32 + lane];
        float4 v2 = m4[(size_t)s2 * 32 + lane];
        float4 v3 = m4[(size_t)s3 * 32 + lane];
        acc.x += (v0.x + v1.x) + (v2.x + v3.x);
        acc.y += (v0.y + v1.y) + (v2.y + v3.y);
        acc.z += (v0.z + v1.z) + (v2.z + v3.z);
        acc.w += (v0.w + v1.w) + (v2.w + v3.w);
    }
    for (; i < e; ++i) {
        float4 v = m4[(size_t)g_csrsrc[i] * 32 + lane];
        acc.x += v.x; acc.y += v.y; acc.z += v.z; acc.w += v.w;
    }
    reinterpret_cast<float4*>(g_agg)[(size_t)warp * 32 + lane] = acc;
}

// GRU gates
__global__ void gate_k(const float* __restrict__ bih, const float* __restrict__ bhh) {
    int idx = blockIdx.x * blockDim.x + threadIdx.x;
    if (idx >= NN * CC) return;
    int c = idx & (CC - 1);
    size_t n = (size_t)(idx >> 7);
    const float* Gp = g_G + n * (3 * CC);
    float Gr = Gp[c], Gz = Gp[CC + c], Gn = Gp[2 * CC + c];
    float Hnv = g_Hn[n * CC + c];
    float r = 1.f / (1.f + expf(-(Gr + bih[c] + bhh[c])));
    float z = 1.f / (1.f + expf(-(Gz + bih[CC + c] + bhh[CC + c])));
    float nn = tanhf((Gn - Hnv) + bih[2 * CC + c] + r * (Hnv + bhh[2 * CC + c]));
    float h = g_h[n * CC + c];
    g_h[n * CC + c] = (1.f - z) * nn + z * h;
}

// ---------------- readout ----------------
__global__ void zero_colsum_k() { if (threadIdx.x < CC) g_colsum[threadIdx.x] = 0.f; }

__global__ void reduce_cols_k() {
    int c = threadIdx.x;
    float acc = 0.f;
    for (int n = blockIdx.x; n < NN; n += gridDim.x) {
        float v = g_h[(size_t)n * CC + c];
        acc += (v >= 0.f) ? v : NEG_SLOPE * v;
    }
    atomicAdd(&g_colsum[c], acc);
}

__global__ void finalize_k(const float* __restrict__ wpred, const float* __restrict__ bpred,
                           float* __restrict__ out) {
    int lane = threadIdx.x;
    float s = 0.f;
    for (int c = lane; c < CC; c += 32) s += g_colsum[c] * wpred[c];
    for (int o = 16; o; o >>= 1) s += __shfl_xor_sync(0xFFFFFFFFu, s, o);
    if (lane == 0) out[0] = s * (1.0f / (float)NN) + bpred[0];
}

// ---------------- launch ----------------
extern "C" void kernel_launch(void* const* d_in, const int* in_sizes, int n_in,
                              void* d_out, int out_size) {
    const float* x      = (const float*)d_in[0];
    const void*  edges  = d_in[1];
    const float* W_in   = (const float*)d_in[2];
    const float* W_mpnn = (const float*)d_in[3];
    const float* W_ih   = (const float*)d_in[4];
    const float* W_hh   = (const float*)d_in[5];
    const float* b_ih   = (const float*)d_in[6];
    const float* b_hh   = (const float*)d_in[7];
    const float* W_pred = (const float*)d_in[8];
    const float* b_pred = (const float*)d_in[9];
    float* out = (float*)d_out;

    void *p_h, *p_m, *p_agg, *p_G, *p_Hn, *p_Wt;
    cudaGetSymbolAddress(&p_h,   g_h);
    cudaGetSymbolAddress(&p_m,   g_m);
    cudaGetSymbolAddress(&p_agg, g_agg);
    cudaGetSymbolAddress(&p_G,   g_G);
    cudaGetSymbolAddress(&p_Hn,  g_Hn);
    cudaGetSymbolAddress(&p_Wt,  g_Wt);
    float* h_  = (float*)p_h;
    float* m_  = (float*)p_m;
    float* ag_ = (float*)p_agg;
    float* G_  = (float*)p_G;
    float* Hn_ = (float*)p_Hn;
    float* Wt_ = (float*)p_Wt;

    const int NB = (NN + 1023) / 1024;   // 98

    // CSR build
    detect_k<<<1, 32>>>(edges);
    zero_deg_k<<<128, 256>>>();
    hist_k<<<512, 256>>>(edges);
    scan1_k<<<NB, 1024>>>();
    scan2_k<<<1, 32>>>(NB);
    scan3_k<<<NB, 1024>>>();
    scatter_k<<<512, 256>>>(edges);

    dim3 grid1((NN + 127) / 128, 1);
    dim3 grid3((NN + 127) / 128, 3);

    // h = x @ W_in^T   (M=NN, N=128, K=64)
    mma_gemm_nt<<<grid1, 256>>>(x, FIN, x, FIN, FIN,
                                W_in, FIN, W_in, FIN, FIN,
                                h_, CC, NN, FIN);

    for (int step = 0; step < NSTEP; ++step) {
        // m = h @ W_mpnn[step] = h @ (W_mpnn[step]^T)^T
        transpose_k<<<64, 256>>>(W_mpnn + (size_t)step * CC * CC);
        mma_gemm_nt<<<grid1, 256>>>(h_, CC, h_, CC, CC,
                                    Wt_, CC, Wt_, CC, CC,
                                    m_, CC, NN, CC);

        // agg = scatter_add(m[src] -> dst) via CSR gather
        aggregate_k<<<NN / 8, 256>>>();

        // G = [agg | h] @ [W_ih | W_hh]^T   (M=NN, N=384, K=256)
        mma_gemm_nt<<<grid3, 256>>>(ag_, CC, h_, CC, CC,
                                    W_ih, CC, W_hh, CC, CC,
                                    G_, 3 * CC, NN, 2 * CC);

        // Hn = h @ W_hh[2C:,:]^T   (M=NN, N=128, K=128)
        mma_gemm_nt<<<grid1, 256>>>(h_, CC, h_, CC, CC,
                                    W_hh + 2 * CC * CC, CC, W_hh + 2 * CC * CC, CC, CC,
                                    Hn_, CC, NN, CC);

        gate_k<<<(NN * CC) / 256, 256>>>(b_ih, b_hh);
    }

    // leaky-relu -> column sums -> dot with W_pred, divide by N
    zero_colsum_k<<<1, 128>>>();
    reduce_cols_k<<<2048, 128>>>();
    finalize_k<<<1, 32>>>(W_pred, b_pred, out);
}